// round 9
// baseline (speedup 1.0000x reference)
#include <cuda_runtime.h>
#include <cuda_fp16.h>

#define CCH 256        // channels (all levels)
#define NIMG 2         // batch
#define NBINS 49       // 7*7
#define SPITCH 260     // staging pitch in floats (CCH+4): 16B-aligned
#define HTAP 400       // 25 bins * 16 taps (per-phase table)
#define L0_TILES 8192  // 512 hw-tiles * 8 channel-tiles * 2 images
#define L0_GRID 444    // ~3 CTAs/SM -> single wave (leaves slots for pool)

// NHWC fp16 scratch for all 4 levels (element offsets):
// L0 @ 0, L1 @ 33,554,432, L2 @ 41,943,040, L3 @ 44,040,192 (44,564,480 halves = 89 MB)
__device__ __half g_nhwc[44564480];

__constant__ long long c_lvl_off[4] = {0LL, 33554432LL, 41943040LL, 44040192LL};

// ---------------------------------------------------------------------------
// Transpose one 128x32 (hw x c) tile: NCHW fp32 -> NHWC fp16.
// Block (8,32); 4 front-batched LDG.128 (MLP=4).
// ---------------------------------------------------------------------------
__device__ __forceinline__ void transpose_tile(
    const float* __restrict__ src, __half* __restrict__ dst_lvl,
    float (*tile)[32][33], int HW, int hw0, int c0, int n, int tx, int ty)
{
    const float* s = src + (size_t)n * CCH * HW + (size_t)(c0 + ty) * HW + hw0 + tx * 4;

#pragma unroll
    for (int j = 0; j < 4; ++j) {
        const float4 v = *reinterpret_cast<const float4*>(s + j * 32);
        tile[j][ty][tx * 4 + 0] = v.x;
        tile[j][ty][tx * 4 + 1] = v.y;
        tile[j][ty][tx * 4 + 2] = v.z;
        tile[j][ty][tx * 4 + 3] = v.w;
    }
    __syncthreads();

    __half* dst = dst_lvl + (size_t)n * HW * CCH + (size_t)(hw0 + ty) * CCH + c0 + tx * 4;

#pragma unroll
    for (int j = 0; j < 4; ++j) {
        const __half2 a = __floats2half2_rn(tile[j][tx * 4 + 0][ty], tile[j][tx * 4 + 1][ty]);
        const __half2 b = __floats2half2_rn(tile[j][tx * 4 + 2][ty], tile[j][tx * 4 + 3][ty]);
        uint2 o;
        o.x = *reinterpret_cast<const unsigned int*>(&a);
        o.y = *reinterpret_cast<const unsigned int*>(&b);
        *reinterpret_cast<uint2*>(dst + (size_t)j * 32 * CCH) = o;
    }
}

// Levels 1..3 transpose (small, ~45 MB r+w). grid (168, 8, 2), block (8,32).
__global__ __launch_bounds__(256) void transpose_small(
    const float* __restrict__ f1, const float* __restrict__ f2,
    const float* __restrict__ f3)
{
    __shared__ float tile[4][32][33];

    const int bx = blockIdx.x;
    int lvl, tb;
    const float* src;
    if (bx < 128)      { lvl = 1; tb = bx;       src = f1; }
    else if (bx < 160) { lvl = 2; tb = bx - 128; src = f2; }
    else               { lvl = 3; tb = bx - 160; src = f3; }

    const int HW = (256 >> lvl) * (256 >> lvl);
    transpose_tile(src, g_nhwc + c_lvl_off[lvl], tile, HW, tb * 128,
                   blockIdx.y * 32, blockIdx.z,
                   threadIdx.x, threadIdx.y);
}

// Level 0 transpose: persistent single-wave kernel looping over all tiles.
// Triggers programmatic launch completion immediately so the following
// PDL pool kernel (levels 1-3, no data dependency on L0) can co-schedule.
__global__ __launch_bounds__(256) void transpose_l0(const float* __restrict__ f0)
{
    cudaTriggerProgrammaticLaunchCompletion();

    __shared__ float tile[4][32][33];
    const int tx = threadIdx.x, ty = threadIdx.y;

    for (int it = blockIdx.x; it < L0_TILES; it += L0_GRID) {
        const int tb = it & 511;
        const int c0 = ((it >> 9) & 7) * 32;
        const int n  = it >> 12;
        transpose_tile(f0, g_nhwc, tile, 65536, tb * 128, c0, n, tx, ty);
        __syncthreads();   // smem reuse barrier before next iteration
    }
}

// ---------------------------------------------------------------------------
// ROIAlign pooler over fp16 NHWC scratch (R8 math, unchanged). TWO CTAs/box.
// Template L0ONLY filters boxes by level so the lvl>=1 instance can run
// concurrently with transpose_l0 under PDL.
// ---------------------------------------------------------------------------
template <bool L0ONLY>
__global__ __launch_bounds__(256) void roi_pool_kernel(
    const float* __restrict__ boxes, float* __restrict__ out, int R)
{
    __shared__ float s_out[25 * SPITCH];           // 26,000 B
    __shared__ uint2 s_tap[HTAP];                  // 3,200 B
    __shared__ int   s_i0[2][14], s_i1[2][14];
    __shared__ float s_h[2][14],  s_l[2][14];

    const int bid   = blockIdx.x;
    const int m     = bid >> 1;
    const int phase = bid & 1;
    const int tid   = threadIdx.x;

    const int b0   = phase ? 25 : 0;
    const int bcnt = phase ? 24 : 25;

    const float bx1 = __ldg(boxes + 4 * m + 0);
    const float by1 = __ldg(boxes + 4 * m + 1);
    const float bx2 = __ldg(boxes + 4 * m + 2);
    const float by2 = __ldg(boxes + 4 * m + 3);

    const float area = fmaxf((bx2 - bx1) * (by2 - by1), 0.0f);
    const float sz   = sqrtf(area);
    int lvl = (int)floorf(4.0f + log2f(sz / 224.0f + 1e-8f));
    lvl = min(max(lvl, 2), 5) - 2;                 // 0..3

    if ((lvl == 0) != L0ONLY) return;              // level filter

    const int   Hd    = 256 >> lvl;
    const int   Wd    = Hd;
    const float scale = 0.25f / (float)(1 << lvl);
    const int   n     = m / R;

    const __half* fbase = g_nhwc + c_lvl_off[lvl] + (size_t)n * Hd * Wd * CCH;

    if (tid < 28) {
        const int axis = tid / 14;                 // 0 = x, 1 = y
        const int k    = tid - axis * 14;
        const float c1 = axis ? by1 : bx1;
        const float c2 = axis ? by2 : bx2;
        const int  lim = Hd;
        const float start = c1 * scale - 0.5f;
        const float bsz   = (c2 * scale - 0.5f - start) * (1.0f / 7.0f);
        const float off   = (float)(k >> 1) + ((k & 1) ? 0.75f : 0.25f);
        const float t     = start + off * bsz;
        const bool  v     = (t >= -1.0f) && (t <= (float)lim);
        const float tc    = fminf(fmaxf(t, 0.0f), (float)(lim - 1));
        const int   i0    = (int)tc;
        const int   i1    = min(i0 + 1, lim - 1);
        const float l     = tc - (float)i0;
        s_i0[axis][k] = i0;
        s_i1[axis][k] = i1;
        s_l[axis][k]  = v ? l : 0.0f;
        s_h[axis][k]  = v ? (1.0f - l) : 0.0f;
    }
    __syncthreads();

    // Per-phase tap table: i -> local bin i>>4, tap i&15 ([3]=sy,[2]=sx,[1]=cy,[0]=cx).
    for (int i = tid; i < bcnt * 16; i += 256) {
        const int bin = b0 + (i >> 4);
        const int t   = i & 15;
        const int py  = bin / 7;
        const int px  = bin - py * 7;
        const int iy  = py * 2 + (t >> 3);
        const int ix  = px * 2 + ((t >> 2) & 1);
        const int cy  = (t >> 1) & 1;
        const int cx  = t & 1;
        const int   yy = cy ? s_i1[1][iy] : s_i0[1][iy];
        const int   xx = cx ? s_i1[0][ix] : s_i0[0][ix];
        const float wy = cy ? s_l[1][iy]  : s_h[1][iy];
        const float wx = cx ? s_l[0][ix]  : s_h[0][ix];
        const __half2 w = __float2half2_rn(wy * wx * 0.25f);
        uint2 e;
        e.x = (unsigned int)(yy * Wd + xx);
        e.y = *reinterpret_cast<const unsigned int*>(&w);
        s_tap[i] = e;
    }
    __syncthreads();

    const int q  = tid & 31;
    const int bs = tid >> 5;
    const uint4* base16 = reinterpret_cast<const uint4*>(fbase) + q;
    float* outm = out + (size_t)m * (NBINS * CCH);

    for (int bb = bs; bb < bcnt; bb += 8) {
        const int tb = bb * 16;
        float2 facc[4] = {{0.f,0.f},{0.f,0.f},{0.f,0.f},{0.f,0.f}};
#pragma unroll
        for (int smp = 0; smp < 4; ++smp) {
            __half2 hacc[4];
#pragma unroll
            for (int t = 0; t < 4; ++t) {
                const uint2 e = s_tap[tb + smp * 4 + t];   // LDS.64 broadcast
                const __half2 w = *reinterpret_cast<const __half2*>(&e.y);
                const uint4 u = __ldg(base16 + (size_t)e.x * 32);
                const __half2* h = reinterpret_cast<const __half2*>(&u);
#pragma unroll
                for (int j = 0; j < 4; ++j)
                    hacc[j] = (t == 0) ? __hmul2(h[j], w)
                                       : __hfma2(h[j], w, hacc[j]);
            }
#pragma unroll
            for (int j = 0; j < 4; ++j) {
                const float2 f = __half22float2(hacc[j]);
                facc[j].x += f.x;
                facc[j].y += f.y;
            }
        }
        float4* s4 = reinterpret_cast<float4*>(s_out + bb * SPITCH + q * 8);
        s4[0] = make_float4(facc[0].x, facc[0].y, facc[1].x, facc[1].y);
        s4[1] = make_float4(facc[2].x, facc[2].y, facc[3].x, facc[3].y);
    }
    __syncthreads();

    // Transposed dump: compile-time bin counts (magic-multiply div).
    if (phase == 0) {
        for (int i = tid; i < 25 * CCH; i += 256) {
            const int c  = i / 25;
            const int bb = i - c * 25;
            outm[c * NBINS + bb] = s_out[bb * SPITCH + c];
        }
    } else {
        for (int i = tid; i < 24 * CCH; i += 256) {
            const int c  = i / 24;
            const int bb = i - c * 24;
            outm[c * NBINS + 25 + bb] = s_out[bb * SPITCH + c];
        }
    }
}

// ---------------------------------------------------------------------------
extern "C" void kernel_launch(void* const* d_in, const int* in_sizes, int n_in,
                              void* d_out, int out_size)
{
    const float* f0    = (const float*)d_in[0];
    const float* f1    = (const float*)d_in[1];
    const float* f2    = (const float*)d_in[2];
    const float* f3    = (const float*)d_in[3];
    const float* boxes = (const float*)d_in[4];
    float*       out   = (float*)d_out;

    const int M = in_sizes[4] / 4;   // 1024 boxes
    const int R = M / NIMG;          // 512 per image

    // 1) transpose levels 1-3 (completes before transpose_l0 starts)
    transpose_small<<<dim3(168, CCH / 32, NIMG), dim3(8, 32)>>>(f1, f2, f3);

    // 2) L0 transpose: single-wave persistent, triggers PDL completion early
    transpose_l0<<<L0_GRID, dim3(8, 32)>>>(f0);

    // 3) pool for level>=1 boxes: PDL -> co-schedules with transpose_l0.
    //    Its only dependency (transpose_small) completed before transpose_l0
    //    started, so no grid-dependency sync is needed.
    {
        cudaLaunchConfig_t cfg = {};
        cfg.gridDim  = dim3((unsigned)(M * 2));
        cfg.blockDim = dim3(256);
        cfg.stream   = 0;
        cudaLaunchAttribute attr[1];
        attr[0].id = cudaLaunchAttributeProgrammaticStreamSerialization;
        attr[0].val.programmaticStreamSerializationAllowed = 1;
        cfg.attrs    = attr;
        cfg.numAttrs = 1;
        cudaLaunchKernelEx(&cfg, roi_pool_kernel<false>, boxes, out, R);
    }

    // 4) pool for level-0 boxes: plain launch, waits for everything prior
    roi_pool_kernel<true><<<M * 2, 256>>>(boxes, out, R);
}